// round 6
// baseline (speedup 1.0000x reference)
#include <cuda_runtime.h>
#include <cuda_bf16.h>
#include <math.h>
#include <stdint.h>

#define NLIG 1024
#define NPKT 8192
#define HID 256
#define ADIM 512
#define TABN 4096
#define CUTOFF 10.0f

#define G 8                 // ligands per block
#define NGRP (NLIG / G)     // 128 blocks
#define BLK2 512            // threads in grouped attn
#define TILE 64             // atoms per tile
#define CAP2 NPKT           // union can never exceed NPKT -> no overflow handling

// ---------------- device scratch ----------------
__device__ __nv_bfloat16 g_Abf[NPKT * ADIM];
__device__ __nv_bfloat16 g_hligbf[NLIG * HID];
__device__ __nv_bfloat16 g_kwbf[ADIM * HID];
__device__ __nv_bfloat16 g_vwbf[ADIM * HID];
__device__ __nv_bfloat16 g_qwbf[HID * HID];
__device__ __nv_bfloat16 g_Kbf[NPKT * HID];
__device__ __nv_bfloat16 g_Vbf[NPKT * HID];
__device__ float  g_Q[NLIG * HID];
__device__ float  g_hatt[NLIG * HID];
__device__ float  g_t2[NLIG * HID];
__device__ float4 g_cm[NLIG];
__device__ float4 g_xp4[NPKT];
__device__ float4 g_tab[TABN];
__device__ int    g_order[NLIG];

// ---------------- helpers ----------------
__device__ __forceinline__ float wsum(float v) {
    v += __shfl_xor_sync(0xffffffffu, v, 16);
    v += __shfl_xor_sync(0xffffffffu, v, 8);
    v += __shfl_xor_sync(0xffffffffu, v, 4);
    v += __shfl_xor_sync(0xffffffffu, v, 2);
    v += __shfl_xor_sync(0xffffffffu, v, 1);
    return v;
}
__device__ __forceinline__ uint32_t smem_u32(const void* p) {
    return (uint32_t)__cvta_generic_to_shared(p);
}
__device__ __forceinline__ void cp_async16(uint32_t dst, const void* src) {
    asm volatile("cp.async.cg.shared.global [%0], [%1], 16;" :: "r"(dst), "l"(src));
}
__device__ __forceinline__ float dot8(const float4& qa, const float4& qb, const uint4& kr) {
    float2 k0 = __bfloat1622float2(*(const __nv_bfloat162*)&kr.x);
    float2 k1 = __bfloat1622float2(*(const __nv_bfloat162*)&kr.y);
    float2 k2 = __bfloat1622float2(*(const __nv_bfloat162*)&kr.z);
    float2 k3 = __bfloat1622float2(*(const __nv_bfloat162*)&kr.w);
    return qa.x * k0.x + qa.y * k0.y + qa.z * k1.x + qa.w * k1.y +
           qb.x * k2.x + qb.y * k2.y + qb.z * k3.x + qb.w * k3.y;
}

// ---------------- spatial sort of ligands (rank sort, deterministic) -----
__global__ void sort_lig(const float* __restrict__ x_lig) {
    __shared__ uint32_t keys[NLIG];
    int t = threadIdx.x;
    float x = x_lig[t * 3 + 0], y = x_lig[t * 3 + 1], z = x_lig[t * 3 + 2];
    int cx = min(7, max(0, (int)(x * (8.0f / 30.0f))));
    int cy = min(7, max(0, (int)(y * (8.0f / 30.0f))));
    int cz = min(7, max(0, (int)(z * (8.0f / 30.0f))));
    uint32_t key = ((uint32_t)(((cx << 3) | cy) << 3 | cz) << 10) | (uint32_t)t;
    keys[t] = key;
    __syncthreads();
    int rank = 0;
    for (int j = 0; j < NLIG; j++) rank += (keys[j] < key) ? 1 : 0;
    g_order[rank] = t;
}

// ---------------- fused prep: table + xp4 ----------------
__global__ void prep_misc(const float* __restrict__ xp,
                          const float* __restrict__ e1w,
                          const float* __restrict__ e1b,
                          const float* __restrict__ e2w,
                          const float* __restrict__ e2b) {
    int b = blockIdx.x, t = threadIdx.x;
    if (b < 16) {
        int e = b * 256 + t;
        float d = (float)e * (CUTOFF / (float)(TABN - 1));
        float a0 = e2b[0], a1 = e2b[1], a2 = e2b[2], a3 = e2b[3];
        for (int u = 0; u < HID; u++) {
            float z = fmaf(d, e1w[u], e1b[u]);
            float s = z / (1.0f + expf(-z));
            a0 = fmaf(s, e2w[u * 4 + 0], a0);
            a1 = fmaf(s, e2w[u * 4 + 1], a1);
            a2 = fmaf(s, e2w[u * 4 + 2], a2);
            a3 = fmaf(s, e2w[u * 4 + 3], a3);
        }
        g_tab[e] = make_float4(a0, a1, a2, a3);
    } else {
        int j = (b - 16) * 256 + t;
        g_xp4[j] = make_float4(xp[j * 3 + 0], xp[j * 3 + 1], xp[j * 3 + 2], 0.f);
    }
}

// ---------------- fused fp32 -> bf16 ----------------
#define SZ0 (NPKT * ADIM)
#define SZ1 (SZ0 + NLIG * HID)
#define SZ2 (SZ1 + ADIM * HID)
#define SZ3 (SZ2 + ADIM * HID)
#define SZ4 (SZ3 + HID * HID)
__global__ void f2bf_all(const float* __restrict__ h_atm, const float* __restrict__ h_lig,
                         const float* __restrict__ kw, const float* __restrict__ vw,
                         const float* __restrict__ qw) {
    long i4 = (long)(blockIdx.x * 256 + threadIdx.x) * 4;
    const float* src;
    __nv_bfloat16* dst;
    long off;
    if (i4 < SZ0)      { src = h_atm; dst = g_Abf;    off = i4; }
    else if (i4 < SZ1) { src = h_lig; dst = g_hligbf; off = i4 - SZ0; }
    else if (i4 < SZ2) { src = kw;    dst = g_kwbf;   off = i4 - SZ1; }
    else if (i4 < SZ3) { src = vw;    dst = g_vwbf;   off = i4 - SZ2; }
    else if (i4 < SZ4) { src = qw;    dst = g_qwbf;   off = i4 - SZ3; }
    else return;
    float4 v = *(const float4*)(src + off);
    *(__nv_bfloat162*)(dst + off)     = __floats2bfloat162_rn(v.x, v.y);
    *(__nv_bfloat162*)(dst + off + 2) = __floats2bfloat162_rn(v.z, v.w);
}

// ---------------- bf16 tensor-core GEMM, 2-stage cp.async pipeline ----------
template <bool FLOATOUT>
__global__ __launch_bounds__(256) void gemm_mma(const __nv_bfloat16* __restrict__ A,
                                                const __nv_bfloat16* __restrict__ W,
                                                const float* __restrict__ bias,
                                                void* __restrict__ Cv,
                                                int M, int N, int K) {
    __shared__ __nv_bfloat16 As[2][64][40];
    __shared__ __nv_bfloat16 Bs[2][32][72];
    const int t = threadIdx.x;
    const int warp = t >> 5, lane = t & 31;
    const int wm = warp >> 1, wn = warp & 1;
    const int bm = blockIdx.x * 64, bn = blockIdx.y * 64;
    const int ar = t >> 2, ac = (t & 3) * 8;
    const int br = t >> 3, bc = (t & 7) * 8;

    float acc[4][4];
#pragma unroll
    for (int nt = 0; nt < 4; nt++)
#pragma unroll
        for (int r = 0; r < 4; r++) acc[nt][r] = 0.f;

    const int NK = K / 32;
    cp_async16(smem_u32(&As[0][ar][ac]), A + (size_t)(bm + ar) * K + ac);
    cp_async16(smem_u32(&Bs[0][br][bc]), W + (size_t)br * N + bn + bc);
    asm volatile("cp.async.commit_group;");

    for (int kt = 0; kt < NK; kt++) {
        if (kt + 1 < NK) {
            int s = (kt + 1) & 1, ko = (kt + 1) * 32;
            cp_async16(smem_u32(&As[s][ar][ac]), A + (size_t)(bm + ar) * K + ko + ac);
            cp_async16(smem_u32(&Bs[s][br][bc]), W + (size_t)(ko + br) * N + bn + bc);
            asm volatile("cp.async.commit_group;");
            asm volatile("cp.async.wait_group 1;");
        } else {
            asm volatile("cp.async.wait_group 0;");
        }
        __syncthreads();
        const int st = kt & 1;
#pragma unroll
        for (int kk = 0; kk < 32; kk += 16) {
            uint32_t a[4];
            {
                int row = wm * 16 + (lane & 15);
                int col = kk + 8 * (lane >> 4);
                uint32_t addr = smem_u32(&As[st][row][col]);
                asm volatile("ldmatrix.sync.aligned.m8n8.x4.shared.b16 {%0,%1,%2,%3}, [%4];"
                             : "=r"(a[0]), "=r"(a[1]), "=r"(a[2]), "=r"(a[3])
                             : "r"(addr));
            }
            uint32_t b[4][2];
#pragma unroll
            for (int nt2 = 0; nt2 < 2; nt2++) {
                int row = kk + (lane & 15);
                int col = wn * 32 + nt2 * 16 + 8 * (lane >> 4);
                uint32_t addr = smem_u32(&Bs[st][row][col]);
                uint32_t b0, b1, b2, b3;
                asm volatile("ldmatrix.sync.aligned.m8n8.x4.trans.shared.b16 {%0,%1,%2,%3}, [%4];"
                             : "=r"(b0), "=r"(b1), "=r"(b2), "=r"(b3)
                             : "r"(addr));
                b[nt2 * 2 + 0][0] = b0; b[nt2 * 2 + 0][1] = b1;
                b[nt2 * 2 + 1][0] = b2; b[nt2 * 2 + 1][1] = b3;
            }
#pragma unroll
            for (int nt = 0; nt < 4; nt++) {
                asm volatile(
                    "mma.sync.aligned.m16n8k16.row.col.f32.bf16.bf16.f32 "
                    "{%0,%1,%2,%3}, {%4,%5,%6,%7}, {%8,%9}, {%0,%1,%2,%3};"
                    : "+f"(acc[nt][0]), "+f"(acc[nt][1]), "+f"(acc[nt][2]), "+f"(acc[nt][3])
                    : "r"(a[0]), "r"(a[1]), "r"(a[2]), "r"(a[3]),
                      "r"(b[nt][0]), "r"(b[nt][1]));
            }
        }
        __syncthreads();
    }

#pragma unroll
    for (int nt = 0; nt < 4; nt++) {
        int row0 = bm + wm * 16 + (lane >> 2);
        int col = bn + wn * 32 + nt * 8 + (lane & 3) * 2;
        float bi0 = bias[col], bi1 = bias[col + 1];
        float v0 = acc[nt][0] + bi0, v1 = acc[nt][1] + bi1;
        float v2 = acc[nt][2] + bi0, v3 = acc[nt][3] + bi1;
        if (FLOATOUT) {
            float* C = (float*)Cv;
            *(float2*)(C + (size_t)row0 * N + col) = make_float2(v0, v1);
            *(float2*)(C + (size_t)(row0 + 8) * N + col) = make_float2(v2, v3);
        } else {
            __nv_bfloat16* C = (__nv_bfloat16*)Cv;
            *(__nv_bfloat162*)(C + (size_t)row0 * N + col) = __floats2bfloat162_rn(v0, v1);
            *(__nv_bfloat162*)(C + (size_t)(row0 + 8) * N + col) = __floats2bfloat162_rn(v2, v3);
        }
    }
}

// ---------------- grouped flash-style attention ----------------
struct SM2 {
    unsigned short list[CAP2];        // 16 KB
    unsigned char  amask[CAP2];       // 8 KB
    float Q_s[G][HID];                // 8 KB
    __nv_bfloat16 Vt[2][TILE][HID];   // 64 KB
    float Sraw[TILE][G][4];           // 8 KB (dots -> probs in place)
    float4 xq[TILE];                  // 1 KB
    float wpm[16][G][4];              // 2 KB
    float wpl[16][G][4];              // 2 KB
    float wpc[16][G][12];             // 6 KB
    float m_s[G][4], l_s[G][4], sc_s[G][4];
    float cacc[G][4][3];
    float4 xl[G];
    int   ligidx[G];
    int   woff[16];
    int   s_cnt;
};

__global__ __launch_bounds__(BLK2, 1) void attn_group(const float* __restrict__ x_lig) {
    extern __shared__ char smraw[];
    SM2* sm = (SM2*)smraw;
    const int t = threadIdx.x;
    const int w = t >> 5, lane = t & 31;
    const int g = blockIdx.x;

    if (t < G) {
        int li = g_order[g * G + t];
        sm->ligidx[t] = li;
        sm->xl[t] = make_float4(x_lig[li * 3 + 0], x_lig[li * 3 + 1], x_lig[li * 3 + 2], 0.f);
    }
    if (t < 32) { sm->m_s[t >> 2][t & 3] = -1e30f; sm->l_s[t >> 2][t & 3] = 0.f; }
    if (t < 96) { int L = t / 12, r = t % 12; sm->cacc[L][r / 3][r % 3] = 0.f; }
    __syncthreads();

#pragma unroll
    for (int r = 0; r < 4; r++) {
        int idx = r * BLK2 + t;
        int L = idx >> 8, d = idx & 255;
        sm->Q_s[L][d] = g_Q[(size_t)sm->ligidx[L] * HID + d] * 0.125f;
    }

    // ---- union compaction with per-ligand mask bits ----
    float lx[G], ly[G], lz[G];
#pragma unroll
    for (int L = 0; L < G; L++) {
        float4 p = sm->xl[L];
        lx[L] = p.x; ly[L] = p.y; lz[L] = p.z;
    }
    int cnt = 0;
    uint32_t am[4] = {0, 0, 0, 0};
    const int jb = t * 16;
#pragma unroll 2
    for (int k = 0; k < 16; k++) {
        float4 xp = g_xp4[jb + k];
        uint32_t mb = 0;
#pragma unroll
        for (int L = 0; L < G; L++) {
            float dx = xp.x - lx[L], dy = xp.y - ly[L], dz = xp.z - lz[L];
            float d2 = dx * dx + dy * dy + dz * dz;
            mb |= (d2 < CUTOFF * CUTOFF ? 1u : 0u) << L;
        }
        cnt += (mb != 0);
        am[k >> 2] |= mb << ((k & 3) * 8);
    }
    int inc = cnt;
#pragma unroll
    for (int off = 1; off < 32; off <<= 1) {
        int v = __shfl_up_sync(0xffffffffu, inc, off);
        if (lane >= off) inc += v;
    }
    if (lane == 31) sm->woff[w] = inc;
    __syncthreads();
    if (t == 0) {
        int run = 0;
#pragma unroll
        for (int ww = 0; ww < 16; ww++) { int v = sm->woff[ww]; sm->woff[ww] = run; run += v; }
        sm->s_cnt = run;
    }
    __syncthreads();
    {
        int off = sm->woff[w] + (inc - cnt);
#pragma unroll 2
        for (int k = 0; k < 16; k++) {
            uint32_t mb = (am[k >> 2] >> ((k & 3) * 8)) & 0xffu;
            if (mb) {
                sm->list[off] = (unsigned short)(jb + k);
                sm->amask[off] = (unsigned char)mb;
                off++;
            }
        }
    }
    __syncthreads();
    const int nu = sm->s_cnt;
    const int ntiles = (nu + TILE - 1) / TILE;

    // O accumulators: warp = (ligand, half of dims)
    const int OL = w >> 1, half = w & 1;
    const int D = half * 128 + lane * 4;
    const int Ohead = D >> 6;
    float acc0 = 0.f, acc1 = 0.f, acc2 = 0.f, acc3 = 0.f;

    // V tile loader (all threads; 4 rows per warp)
    auto load_V = [&](int tile) {
        int buf = tile & 1;
#pragma unroll
        for (int i = 0; i < 4; i++) {
            int row = tile * TILE + w * 4 + i;
            if (row < nu) {
                int j = sm->list[row];
                cp_async16(smem_u32(&sm->Vt[buf][w * 4 + i][lane * 8]),
                           g_Vbf + (size_t)j * HID + lane * 8);
            }
        }
        asm volatile("cp.async.commit_group;");
    };
    if (ntiles > 0) load_V(0);

    for (int tile = 0; tile < ntiles; tile++) {
        const int base = tile * TILE;
        const int n_t = min(TILE, nu - base);

        if (t < TILE)
            sm->xq[t] = (t < n_t) ? g_xp4[sm->list[base + t]] : make_float4(0, 0, 0, 0);

        // ---- S phase: warp holds 4 K rows in regs, dots vs all 8 ligands ----
        {
            int na = n_t - w * 4;
            na = na < 0 ? 0 : (na > 4 ? 4 : na);
            uint4 kr[4];
#pragma unroll
            for (int i = 0; i < 4; i++) {
                if (i < na)
                    kr[i] = *(const uint4*)(g_Kbf + (size_t)sm->list[base + w * 4 + i] * HID + lane * 8);
            }
#pragma unroll
            for (int L = 0; L < G; L++) {
                float4 qa = *(const float4*)&sm->Q_s[L][lane * 8];
                float4 qb = *(const float4*)&sm->Q_s[L][lane * 8 + 4];
#pragma unroll
                for (int i = 0; i < 4; i++) {
                    if (i >= na) break;
                    float dp = dot8(qa, qb, kr[i]);
                    dp += __shfl_xor_sync(0xffffffffu, dp, 1);
                    dp += __shfl_xor_sync(0xffffffffu, dp, 2);
                    dp += __shfl_xor_sync(0xffffffffu, dp, 4);
                    if ((lane & 7) == 0) sm->Sraw[w * 4 + i][L][lane >> 3] = dp;
                }
            }
        }
        if (tile + 1 < ntiles) {
            load_V(tile + 1);
            asm volatile("cp.async.wait_group 1;");
        } else {
            asm volatile("cp.async.wait_group 0;");
        }
        __syncthreads();

        // ---- pair phase: bias + mask + tile max ----
        const int a = t >> 3, L = t & 7;
        const bool valid = (a < n_t);
        float s0 = -1e30f, s1 = -1e30f, s2 = -1e30f, s3 = -1e30f;
        float invd = 0.f, rx = 0.f, ry = 0.f, rz = 0.f;
        int mb = 0;
        if (valid) {
            mb = (sm->amask[base + a] >> L) & 1;
            if (mb) {
                float4 xp = sm->xq[a];
                float4 xlL = sm->xl[L];
                rx = xp.x - xlL.x; ry = xp.y - xlL.y; rz = xp.z - xlL.z;
                float d2 = rx * rx + ry * ry + rz * rz;
                float d = sqrtf(d2);
                invd = rsqrtf(d2 + 1e-16f);
                float tp = d * ((float)(TABN - 1) / CUTOFF);
                int k0 = (int)tp;
                k0 = (k0 > TABN - 2) ? (TABN - 2) : k0;
                float fr = tp - (float)k0;
                float4 f0 = g_tab[k0], f1 = g_tab[k0 + 1];
                s0 = sm->Sraw[a][L][0] + f0.x + fr * (f1.x - f0.x);
                s1 = sm->Sraw[a][L][1] + f0.y + fr * (f1.y - f0.y);
                s2 = sm->Sraw[a][L][2] + f0.z + fr * (f1.z - f0.z);
                s3 = sm->Sraw[a][L][3] + f0.w + fr * (f1.w - f0.w);
            }
        }
        {
            float m0 = s0, m1 = s1, m2 = s2, m3 = s3;
            m0 = fmaxf(m0, __shfl_xor_sync(0xffffffffu, m0, 8));
            m1 = fmaxf(m1, __shfl_xor_sync(0xffffffffu, m1, 8));
            m2 = fmaxf(m2, __shfl_xor_sync(0xffffffffu, m2, 8));
            m3 = fmaxf(m3, __shfl_xor_sync(0xffffffffu, m3, 8));
            m0 = fmaxf(m0, __shfl_xor_sync(0xffffffffu, m0, 16));
            m1 = fmaxf(m1, __shfl_xor_sync(0xffffffffu, m1, 16));
            m2 = fmaxf(m2, __shfl_xor_sync(0xffffffffu, m2, 16));
            m3 = fmaxf(m3, __shfl_xor_sync(0xffffffffu, m3, 16));
            if (lane < 8) *(float4*)&sm->wpm[w][lane][0] = make_float4(m0, m1, m2, m3);
        }
        __syncthreads();
        if (t < 32) {
            int L2 = t >> 2, h = t & 3;
            float tm = -1e30f;
#pragma unroll
            for (int w2 = 0; w2 < 16; w2++) tm = fmaxf(tm, sm->wpm[w2][L2][h]);
            float mo = sm->m_s[L2][h];
            float nm = fmaxf(mo, tm);
            sm->sc_s[L2][h] = __expf(mo - nm);
            sm->m_s[L2][h] = nm;
        }
        __syncthreads();

        // ---- probs + l partials + coord partials ----
        float p0 = 0.f, p1 = 0.f, p2 = 0.f, p3 = 0.f;
        if (valid && mb) {
            p0 = __expf(s0 - sm->m_s[L][0]);
            p1 = __expf(s1 - sm->m_s[L][1]);
            p2 = __expf(s2 - sm->m_s[L][2]);
            p3 = __expf(s3 - sm->m_s[L][3]);
        }
        *(float4*)&sm->Sraw[a][L][0] = make_float4(p0, p1, p2, p3);
        {
            float l0 = p0, l1 = p1, l2 = p2, l3 = p3;
            l0 += __shfl_xor_sync(0xffffffffu, l0, 8);
            l1 += __shfl_xor_sync(0xffffffffu, l1, 8);
            l2 += __shfl_xor_sync(0xffffffffu, l2, 8);
            l3 += __shfl_xor_sync(0xffffffffu, l3, 8);
            l0 += __shfl_xor_sync(0xffffffffu, l0, 16);
            l1 += __shfl_xor_sync(0xffffffffu, l1, 16);
            l2 += __shfl_xor_sync(0xffffffffu, l2, 16);
            l3 += __shfl_xor_sync(0xffffffffu, l3, 16);
            if (lane < 8) *(float4*)&sm->wpl[w][lane][0] = make_float4(l0, l1, l2, l3);

            float c[12];
            c[0] = p0 * invd * rx; c[1]  = p0 * invd * ry; c[2]  = p0 * invd * rz;
            c[3] = p1 * invd * rx; c[4]  = p1 * invd * ry; c[5]  = p1 * invd * rz;
            c[6] = p2 * invd * rx; c[7]  = p2 * invd * ry; c[8]  = p2 * invd * rz;
            c[9] = p3 * invd * rx; c[10] = p3 * invd * ry; c[11] = p3 * invd * rz;
#pragma unroll
            for (int j = 0; j < 12; j++) {
                c[j] += __shfl_xor_sync(0xffffffffu, c[j], 8);
                c[j] += __shfl_xor_sync(0xffffffffu, c[j], 16);
            }
            if (lane < 8) {
#pragma unroll
                for (int j = 0; j < 12; j++) sm->wpc[w][lane][j] = c[j];
            }
        }
        __syncthreads();
        if (t < 32) {
            int L2 = t >> 2, h = t & 3;
            float ls = 0.f;
#pragma unroll
            for (int w2 = 0; w2 < 16; w2++) ls += sm->wpl[w2][L2][h];
            sm->l_s[L2][h] = sm->l_s[L2][h] * sm->sc_s[L2][h] + ls;
        }
        if (t < 96) {
            int L2 = t / 12, r = t % 12, h = r / 3, cc = r % 3;
            float cs = 0.f;
#pragma unroll
            for (int w2 = 0; w2 < 16; w2++) cs += sm->wpc[w2][L2][r];
            sm->cacc[L2][h][cc] = sm->cacc[L2][h][cc] * sm->sc_s[L2][h] + cs;
        }
        __syncthreads();

        // ---- O phase: accumulate P @ V from smem tile ----
        {
            float sc = sm->sc_s[OL][Ohead];
            acc0 *= sc; acc1 *= sc; acc2 *= sc; acc3 *= sc;
            const int buf = tile & 1;
            for (int a2 = 0; a2 < n_t; a2++) {
                float pe = sm->Sraw[a2][OL][Ohead];
                __nv_bfloat162 v01 = *(const __nv_bfloat162*)&sm->Vt[buf][a2][D];
                __nv_bfloat162 v23 = *(const __nv_bfloat162*)&sm->Vt[buf][a2][D + 2];
                float2 f01 = __bfloat1622float2(v01);
                float2 f23 = __bfloat1622float2(v23);
                acc0 = fmaf(pe, f01.x, acc0);
                acc1 = fmaf(pe, f01.y, acc1);
                acc2 = fmaf(pe, f23.x, acc2);
                acc3 = fmaf(pe, f23.y, acc3);
            }
        }
        __syncthreads();
    }

    // ---- finalize ----
    {
        float l = sm->l_s[OL][Ohead];
        float linv = (l > 0.f) ? __fdividef(1.f, l) : 0.f;
        float* dst = g_hatt + (size_t)sm->ligidx[OL] * HID + D;
        *(float4*)dst = make_float4(acc0 * linv, acc1 * linv, acc2 * linv, acc3 * linv);
    }
    if (t < 24) {
        int L = t / 3, cc = t % 3;
        float v = 0.f;
#pragma unroll
        for (int h = 0; h < 4; h++) {
            float l = sm->l_s[L][h];
            float linv = (l > 0.f) ? __fdividef(1.f, l) : 0.f;
            v += sm->cacc[L][h][cc] * linv;
        }
        ((float*)&g_cm[sm->ligidx[L]])[cc] = 0.25f * v;
    }
}

// ---------------- merged epilogue GEMM ----------------
__global__ __launch_bounds__(256) void gemm64_epi(const float* __restrict__ A,
                                                  const float* __restrict__ ow,
                                                  const float* __restrict__ ob,
                                                  const float* __restrict__ c1w,
                                                  const float* __restrict__ c1b,
                                                  const float* __restrict__ h_lig,
                                                  float* __restrict__ out,
                                                  float* __restrict__ t2) {
    const float* W    = blockIdx.z ? c1w : ow;
    const float* bias = blockIdx.z ? c1b : ob;
    const float* R    = blockIdx.z ? nullptr : h_lig;
    float* C          = blockIdx.z ? t2 : out;
    const int N = HID, Kd = HID;

    __shared__ float As[64][16];
    __shared__ float Bs[16][64];
    const int t = threadIdx.x;
    const int tx = t & 15, ty = t >> 4;
    const int bm = blockIdx.x * 64, bn = blockIdx.y * 64;
    const int arow = t >> 2, ac4 = (t & 3) * 4;
    const int brow = t >> 4, bc4 = (t & 15) * 4;

    float acc[4][4];
#pragma unroll
    for (int i = 0; i < 4; i++)
#pragma unroll
        for (int j = 0; j < 4; j++) acc[i][j] = 0.f;

    for (int kt = 0; kt < Kd; kt += 16) {
        float4 av = *(const float4*)(A + (size_t)(bm + arow) * Kd + kt + ac4);
        float4 bv = *(const float4*)(W + (size_t)(kt + brow) * N + bn + bc4);
        *(float4*)&As[arow][ac4] = av;
        *(float4*)&Bs[brow][bc4] = bv;
        __syncthreads();
#pragma unroll
        for (int k = 0; k < 16; k++) {
            float4 bq = *(const float4*)&Bs[k][tx * 4];
            float a0 = As[ty * 4 + 0][k];
            float a1 = As[ty * 4 + 1][k];
            float a2 = As[ty * 4 + 2][k];
            float a3 = As[ty * 4 + 3][k];
            acc[0][0] = fmaf(a0, bq.x, acc[0][0]); acc[0][1] = fmaf(a0, bq.y, acc[0][1]);
            acc[0][2] = fmaf(a0, bq.z, acc[0][2]); acc[0][3] = fmaf(a0, bq.w, acc[0][3]);
            acc[1][0] = fmaf(a1, bq.x, acc[1][0]); acc[1][1] = fmaf(a1, bq.y, acc[1][1]);
            acc[1][2] = fmaf(a1, bq.z, acc[1][2]); acc[1][3] = fmaf(a1, bq.w, acc[1][3]);
            acc[2][0] = fmaf(a2, bq.x, acc[2][0]); acc[2][1] = fmaf(a2, bq.y, acc[2][1]);
            acc[2][2] = fmaf(a2, bq.z, acc[2][2]); acc[2][3] = fmaf(a2, bq.w, acc[2][3]);
            acc[3][0] = fmaf(a3, bq.x, acc[3][0]); acc[3][1] = fmaf(a3, bq.y, acc[3][1]);
            acc[3][2] = fmaf(a3, bq.z, acc[3][2]); acc[3][3] = fmaf(a3, bq.w, acc[3][3]);
        }
        __syncthreads();
    }

#pragma unroll
    for (int i = 0; i < 4; i++) {
        int row = bm + ty * 4 + i;
        int col = bn + tx * 4;
        float v0 = acc[i][0] + bias[col + 0];
        float v1 = acc[i][1] + bias[col + 1];
        float v2 = acc[i][2] + bias[col + 2];
        float v3 = acc[i][3] + bias[col + 3];
        if (R) {
            float4 r = *(const float4*)(R + (size_t)row * N + col);
            v0 += r.x; v1 += r.y; v2 += r.z; v3 += r.w;
        }
        *(float4*)(C + (size_t)row * N + col) = make_float4(v0, v1, v2, v3);
    }
}

// ---------------- finalize: coord scale + x_out ----------------
__global__ __launch_bounds__(256) void finalize_kernel(const float* __restrict__ x_lig,
                                                       const float* __restrict__ c2w,
                                                       const float* __restrict__ c2b,
                                                       float* __restrict__ out) {
    const int lig = blockIdx.x * 8 + (threadIdx.x >> 5);
    const int lane = threadIdx.x & 31;
    const float4* t2 = (const float4*)(g_t2 + (size_t)lig * HID) + lane * 2;
    float4 a = t2[0], b = t2[1];
    const float4* cw = (const float4*)c2w + lane * 2;
    float4 ca = cw[0], cb = cw[1];
    float s = 0.f;
    s = fmaf(a.x / (1.f + __expf(-a.x)), ca.x, s);
    s = fmaf(a.y / (1.f + __expf(-a.y)), ca.y, s);
    s = fmaf(a.z / (1.f + __expf(-a.z)), ca.z, s);
    s = fmaf(a.w / (1.f + __expf(-a.w)), ca.w, s);
    s = fmaf(b.x / (1.f + __expf(-b.x)), cb.x, s);
    s = fmaf(b.y / (1.f + __expf(-b.y)), cb.y, s);
    s = fmaf(b.z / (1.f + __expf(-b.z)), cb.z, s);
    s = fmaf(b.w / (1.f + __expf(-b.w)), cb.w, s);
    s = wsum(s);
    if (lane == 0) {
        s += c2b[0];
        float4 cm = g_cm[lig];
        float* ox = out + (size_t)NLIG * HID + lig * 3;
        ox[0] = x_lig[lig * 3 + 0] + s * cm.x;
        ox[1] = x_lig[lig * 3 + 1] + s * cm.y;
        ox[2] = x_lig[lig * 3 + 2] + s * cm.z;
    }
}

// ---------------- launch ----------------
extern "C" void kernel_launch(void* const* d_in, const int* in_sizes, int n_in,
                              void* d_out, int out_size) {
    const float* h_lig = (const float*)d_in[0];
    const float* x_lig = (const float*)d_in[1];
    const float* h_atm = (const float*)d_in[2];
    const float* x_pkt = (const float*)d_in[3];
    const float* qw = (const float*)d_in[4];
    const float* qb = (const float*)d_in[5];
    const float* kw = (const float*)d_in[6];
    const float* kb = (const float*)d_in[7];
    const float* vw = (const float*)d_in[8];
    const float* vb = (const float*)d_in[9];
    const float* ow = (const float*)d_in[10];
    const float* ob = (const float*)d_in[11];
    const float* e1w = (const float*)d_in[12];
    const float* e1b = (const float*)d_in[13];
    const float* e2w = (const float*)d_in[14];
    const float* e2b = (const float*)d_in[15];
    const float* c1w = (const float*)d_in[16];
    const float* c1b = (const float*)d_in[17];
    const float* c2w = (const float*)d_in[18];
    const float* c2b = (const float*)d_in[19];
    float* out = (float*)d_out;

    __nv_bfloat16 *Abf, *hligbf, *kwbf, *vwbf, *qwbf, *Kbf, *Vbf;
    float *Qp, *hattp, *t2p;
    cudaGetSymbolAddress((void**)&Abf, g_Abf);
    cudaGetSymbolAddress((void**)&hligbf, g_hligbf);
    cudaGetSymbolAddress((void**)&kwbf, g_kwbf);
    cudaGetSymbolAddress((void**)&vwbf, g_vwbf);
    cudaGetSymbolAddress((void**)&qwbf, g_qwbf);
    cudaGetSymbolAddress((void**)&Kbf, g_Kbf);
    cudaGetSymbolAddress((void**)&Vbf, g_Vbf);
    cudaGetSymbolAddress((void**)&Qp, g_Q);
    cudaGetSymbolAddress((void**)&hattp, g_hatt);
    cudaGetSymbolAddress((void**)&t2p, g_t2);

    static bool attr_set = false;
    if (!attr_set) {
        cudaFuncSetAttribute(attn_group, cudaFuncAttributeMaxDynamicSharedMemorySize,
                             (int)sizeof(SM2));
        attr_set = true;
    }

    prep_misc<<<48, 256>>>(x_pkt, e1w, e1b, e2w, e2b);
    f2bf_all<<<(SZ4 / 4 + 255) / 256, 256>>>(h_atm, h_lig, kw, vw, qw);
    sort_lig<<<1, NLIG>>>(x_lig);
    gemm_mma<true><<<dim3(NLIG / 64, HID / 64), 256>>>(hligbf, qwbf, qb, Qp, NLIG, HID, HID);
    gemm_mma<false><<<dim3(NPKT / 64, HID / 64), 256>>>(Abf, kwbf, kb, Kbf, NPKT, HID, ADIM);
    gemm_mma<false><<<dim3(NPKT / 64, HID / 64), 256>>>(Abf, vwbf, vb, Vbf, NPKT, HID, ADIM);
    attn_group<<<NGRP, BLK2, sizeof(SM2)>>>(x_lig);
    gemm64_epi<<<dim3(NLIG / 64, HID / 64, 2), 256>>>(hattp, ow, ob, c1w, c1b, h_lig, out, t2p);
    finalize_kernel<<<NLIG / 8, 256>>>(x_lig, c2w, c2b, out);
}

// round 7
// speedup vs baseline: 2.0939x; 2.0939x over previous
#include <cuda_runtime.h>
#include <cuda_bf16.h>
#include <math.h>
#include <stdint.h>

#define NLIG 1024
#define NPKT 8192
#define HID 256
#define ADIM 512
#define TABN 4096
#define CUTOFF 10.0f
#define CAP 1536
#define ATTN_GRID 512

// ---------------- device scratch ----------------
__device__ __nv_bfloat16 g_Abf[NPKT * ADIM];
__device__ __nv_bfloat16 g_hligbf[NLIG * HID];
__device__ __nv_bfloat16 g_kwbf[ADIM * HID];
__device__ __nv_bfloat16 g_vwbf[ADIM * HID];
__device__ __nv_bfloat16 g_qwbf[HID * HID];
__device__ __nv_bfloat16 g_owbf[HID * HID];
__device__ __nv_bfloat16 g_c1wbf[HID * HID];
__device__ __nv_bfloat16 g_Kbf[NPKT * HID];
__device__ __nv_bfloat16 g_Vbf[NPKT * HID];
__device__ __nv_bfloat16 g_hattbf[NLIG * HID];
__device__ float  g_Q[NLIG * HID];
__device__ float  g_t2[NLIG * HID];
__device__ float4 g_cm[NLIG];
__device__ float4 g_xp4[NPKT];
__device__ float4 g_tab[TABN];

// ---------------- helpers ----------------
__device__ __forceinline__ float wsum(float v) {
    v += __shfl_xor_sync(0xffffffffu, v, 16);
    v += __shfl_xor_sync(0xffffffffu, v, 8);
    v += __shfl_xor_sync(0xffffffffu, v, 4);
    v += __shfl_xor_sync(0xffffffffu, v, 2);
    v += __shfl_xor_sync(0xffffffffu, v, 1);
    return v;
}
__device__ __forceinline__ float wmax(float v) {
    v = fmaxf(v, __shfl_xor_sync(0xffffffffu, v, 16));
    v = fmaxf(v, __shfl_xor_sync(0xffffffffu, v, 8));
    v = fmaxf(v, __shfl_xor_sync(0xffffffffu, v, 4));
    v = fmaxf(v, __shfl_xor_sync(0xffffffffu, v, 2));
    v = fmaxf(v, __shfl_xor_sync(0xffffffffu, v, 1));
    return v;
}
__device__ __forceinline__ uint32_t smem_u32(const void* p) {
    return (uint32_t)__cvta_generic_to_shared(p);
}
__device__ __forceinline__ void cp_async16(uint32_t dst, const void* src) {
    asm volatile("cp.async.cg.shared.global [%0], [%1], 16;" :: "r"(dst), "l"(src));
}
__device__ __forceinline__ float dot8(const float4& qa, const float4& qb, const uint4& kr) {
    float2 k0 = __bfloat1622float2(*(const __nv_bfloat162*)&kr.x);
    float2 k1 = __bfloat1622float2(*(const __nv_bfloat162*)&kr.y);
    float2 k2 = __bfloat1622float2(*(const __nv_bfloat162*)&kr.z);
    float2 k3 = __bfloat1622float2(*(const __nv_bfloat162*)&kr.w);
    return qa.x * k0.x + qa.y * k0.y + qa.z * k1.x + qa.w * k1.y +
           qb.x * k2.x + qb.y * k2.y + qb.z * k3.x + qb.w * k3.y;
}

// ---------------- fused prep: table (blocks 0-15) + xp4 (blocks 16-47) ----
__global__ void prep_misc(const float* __restrict__ xp,
                          const float* __restrict__ e1w,
                          const float* __restrict__ e1b,
                          const float* __restrict__ e2w,
                          const float* __restrict__ e2b) {
    int b = blockIdx.x, t = threadIdx.x;
    if (b < 16) {
        int e = b * 256 + t;
        float d = (float)e * (CUTOFF / (float)(TABN - 1));
        float a0 = e2b[0], a1 = e2b[1], a2 = e2b[2], a3 = e2b[3];
        for (int u = 0; u < HID; u++) {
            float z = fmaf(d, e1w[u], e1b[u]);
            float s = z / (1.0f + expf(-z));
            a0 = fmaf(s, e2w[u * 4 + 0], a0);
            a1 = fmaf(s, e2w[u * 4 + 1], a1);
            a2 = fmaf(s, e2w[u * 4 + 2], a2);
            a3 = fmaf(s, e2w[u * 4 + 3], a3);
        }
        g_tab[e] = make_float4(a0, a1, a2, a3);
    } else {
        int j = (b - 16) * 256 + t;
        g_xp4[j] = make_float4(xp[j * 3 + 0], xp[j * 3 + 1], xp[j * 3 + 2], 0.f);
    }
}

// ---------------- fp32 -> bf16, 4 independent float4 per thread ----------
// block ranges: [0,1024) h_atm | [1024,1088) h_lig | [1088,1104) qw
//               [1104,1136) kw | [1136,1168) vw | [1168,1184) ow | [1184,1200) c1w
__global__ __launch_bounds__(256) void f2bf_all(const float* __restrict__ h_atm,
                                                const float* __restrict__ h_lig,
                                                const float* __restrict__ kw,
                                                const float* __restrict__ vw,
                                                const float* __restrict__ qw,
                                                const float* __restrict__ ow,
                                                const float* __restrict__ c1w) {
    int b = blockIdx.x, t = threadIdx.x;
    const float* src;
    __nv_bfloat16* dst;
    int b0;
    if (b < 1024)      { src = h_atm; dst = g_Abf;    b0 = b; }
    else if (b < 1088) { src = h_lig; dst = g_hligbf; b0 = b - 1024; }
    else if (b < 1104) { src = qw;    dst = g_qwbf;   b0 = b - 1088; }
    else if (b < 1136) { src = kw;    dst = g_kwbf;   b0 = b - 1104; }
    else if (b < 1168) { src = vw;    dst = g_vwbf;   b0 = b - 1136; }
    else if (b < 1184) { src = ow;    dst = g_owbf;   b0 = b - 1168; }
    else               { src = c1w;   dst = g_c1wbf;  b0 = b - 1184; }
    int f4 = b0 * 1024 + t;
#pragma unroll
    for (int r = 0; r < 4; r++) {
        int idx = (f4 + r * 256) * 4;
        float4 v = *(const float4*)(src + idx);
        *(__nv_bfloat162*)(dst + idx)     = __floats2bfloat162_rn(v.x, v.y);
        *(__nv_bfloat162*)(dst + idx + 2) = __floats2bfloat162_rn(v.z, v.w);
    }
}

// ---------------- bf16 tensor-core GEMM, 2-stage cp.async pipeline ----------
// BM=64, BN=64, BK=32; optional fp32 residual R added in epilogue.
template <bool FLOATOUT>
__global__ __launch_bounds__(256) void gemm_mma(const __nv_bfloat16* __restrict__ A,
                                                const __nv_bfloat16* __restrict__ W,
                                                const float* __restrict__ bias,
                                                const float* __restrict__ R,
                                                void* __restrict__ Cv,
                                                int M, int N, int K) {
    __shared__ __nv_bfloat16 As[2][64][40];
    __shared__ __nv_bfloat16 Bs[2][32][72];
    const int t = threadIdx.x;
    const int warp = t >> 5, lane = t & 31;
    const int wm = warp >> 1, wn = warp & 1;
    const int bm = blockIdx.x * 64, bn = blockIdx.y * 64;
    const int ar = t >> 2, ac = (t & 3) * 8;
    const int br = t >> 3, bc = (t & 7) * 8;

    float acc[4][4];
#pragma unroll
    for (int nt = 0; nt < 4; nt++)
#pragma unroll
        for (int r = 0; r < 4; r++) acc[nt][r] = 0.f;

    const int NK = K / 32;
    cp_async16(smem_u32(&As[0][ar][ac]), A + (size_t)(bm + ar) * K + ac);
    cp_async16(smem_u32(&Bs[0][br][bc]), W + (size_t)br * N + bn + bc);
    asm volatile("cp.async.commit_group;");

    for (int kt = 0; kt < NK; kt++) {
        if (kt + 1 < NK) {
            int s = (kt + 1) & 1, ko = (kt + 1) * 32;
            cp_async16(smem_u32(&As[s][ar][ac]), A + (size_t)(bm + ar) * K + ko + ac);
            cp_async16(smem_u32(&Bs[s][br][bc]), W + (size_t)(ko + br) * N + bn + bc);
            asm volatile("cp.async.commit_group;");
            asm volatile("cp.async.wait_group 1;");
        } else {
            asm volatile("cp.async.wait_group 0;");
        }
        __syncthreads();
        const int st = kt & 1;
#pragma unroll
        for (int kk = 0; kk < 32; kk += 16) {
            uint32_t a[4];
            {
                int row = wm * 16 + (lane & 15);
                int col = kk + 8 * (lane >> 4);
                uint32_t addr = smem_u32(&As[st][row][col]);
                asm volatile("ldmatrix.sync.aligned.m8n8.x4.shared.b16 {%0,%1,%2,%3}, [%4];"
                             : "=r"(a[0]), "=r"(a[1]), "=r"(a[2]), "=r"(a[3])
                             : "r"(addr));
            }
            uint32_t b[4][2];
#pragma unroll
            for (int nt2 = 0; nt2 < 2; nt2++) {
                int row = kk + (lane & 15);
                int col = wn * 32 + nt2 * 16 + 8 * (lane >> 4);
                uint32_t addr = smem_u32(&Bs[st][row][col]);
                uint32_t b0, b1, b2, b3;
                asm volatile("ldmatrix.sync.aligned.m8n8.x4.trans.shared.b16 {%0,%1,%2,%3}, [%4];"
                             : "=r"(b0), "=r"(b1), "=r"(b2), "=r"(b3)
                             : "r"(addr));
                b[nt2 * 2 + 0][0] = b0; b[nt2 * 2 + 0][1] = b1;
                b[nt2 * 2 + 1][0] = b2; b[nt2 * 2 + 1][1] = b3;
            }
#pragma unroll
            for (int nt = 0; nt < 4; nt++) {
                asm volatile(
                    "mma.sync.aligned.m16n8k16.row.col.f32.bf16.bf16.f32 "
                    "{%0,%1,%2,%3}, {%4,%5,%6,%7}, {%8,%9}, {%0,%1,%2,%3};"
                    : "+f"(acc[nt][0]), "+f"(acc[nt][1]), "+f"(acc[nt][2]), "+f"(acc[nt][3])
                    : "r"(a[0]), "r"(a[1]), "r"(a[2]), "r"(a[3]),
                      "r"(b[nt][0]), "r"(b[nt][1]));
            }
        }
        __syncthreads();
    }

#pragma unroll
    for (int nt = 0; nt < 4; nt++) {
        int row0 = bm + wm * 16 + (lane >> 2);
        int col = bn + wn * 32 + nt * 8 + (lane & 3) * 2;
        float bi0 = bias[col], bi1 = bias[col + 1];
        float v0 = acc[nt][0] + bi0, v1 = acc[nt][1] + bi1;
        float v2 = acc[nt][2] + bi0, v3 = acc[nt][3] + bi1;
        if (R) {
            float2 r0 = *(const float2*)(R + (size_t)row0 * N + col);
            float2 r1 = *(const float2*)(R + (size_t)(row0 + 8) * N + col);
            v0 += r0.x; v1 += r0.y; v2 += r1.x; v3 += r1.y;
        }
        if (FLOATOUT) {
            float* C = (float*)Cv;
            *(float2*)(C + (size_t)row0 * N + col) = make_float2(v0, v1);
            *(float2*)(C + (size_t)(row0 + 8) * N + col) = make_float2(v2, v3);
        } else {
            __nv_bfloat16* C = (__nv_bfloat16*)Cv;
            *(__nv_bfloat162*)(C + (size_t)row0 * N + col) = __floats2bfloat162_rn(v0, v1);
            *(__nv_bfloat162*)(C + (size_t)(row0 + 8) * N + col) = __floats2bfloat162_rn(v2, v3);
        }
    }
}

// ---------------- attention kernel: persistent, 2 ligands per block ------
__global__ __launch_bounds__(256, 4) void attn_kernel(const float* __restrict__ x_lig) {
    const int t = threadIdx.x;
    const int w = t >> 5, lane = t & 31;
    const int h = lane >> 3;

    __shared__ float q_s[HID];
    __shared__ unsigned short list[CAP];
    __shared__ float4 sarr[CAP];
    __shared__ float wv[8][HID];
    __shared__ float wred[8][4];
    __shared__ float wc[8][4];
    __shared__ float m_s[4], linv_s[4];
    __shared__ float c12[12];
    __shared__ int woff[8];
    __shared__ int s_cnt;
    __shared__ float s_xl[3];

    for (int i = blockIdx.x; i < NLIG; i += ATTN_GRID) {

    if (t < 3) s_xl[t] = x_lig[i * 3 + t];
    q_s[t] = g_Q[(size_t)i * HID + t] * 0.125f;
    __syncthreads();
    const float xlx = s_xl[0], xly = s_xl[1], xlz = s_xl[2];

    // ---- Phase A: deterministic compaction ----
    unsigned msk = 0;
    const int jbase = t * 32;
#pragma unroll 4
    for (int k = 0; k < 32; k++) {
        float4 xp = g_xp4[jbase + k];
        float rx = xp.x - xlx, ry = xp.y - xly, rz = xp.z - xlz;
        float d2 = rx * rx + ry * ry + rz * rz;
        if (d2 < CUTOFF * CUTOFF) msk |= (1u << k);
    }
    int mycnt = __popc(msk);
    int inc = mycnt;
#pragma unroll
    for (int off = 1; off < 32; off <<= 1) {
        int v = __shfl_up_sync(0xffffffffu, inc, off);
        if (lane >= off) inc += v;
    }
    if (lane == 31) woff[w] = inc;
    __syncthreads();
    if (t == 0) {
        int run = 0;
#pragma unroll
        for (int ww = 0; ww < 8; ww++) { int v = woff[ww]; woff[ww] = run; run += v; }
        s_cnt = run;
    }
    __syncthreads();
    int offset = woff[w] + (inc - mycnt);
    unsigned mm = msk;
    while (mm) {
        int k = __ffs(mm) - 1;
        mm &= mm - 1;
        if (offset < CAP) list[offset] = (unsigned short)(jbase + k);
        offset++;
    }
    __syncthreads();
    const int nact = (s_cnt < CAP) ? s_cnt : CAP;

    // ---- B1: warp-per-pair Q.K dots, 4-way unrolled gather ----
    {
        const float4 qa = ((const float4*)q_s)[lane * 2];
        const float4 qb = ((const float4*)q_s)[lane * 2 + 1];
        float* sf = (float*)sarr;
        int p = w;
        for (; p + 24 < nact; p += 32) {
            int j0 = list[p], j1 = list[p + 8], j2 = list[p + 16], j3 = list[p + 24];
            uint4 k0 = *(const uint4*)(g_Kbf + (size_t)j0 * HID + lane * 8);
            uint4 k1 = *(const uint4*)(g_Kbf + (size_t)j1 * HID + lane * 8);
            uint4 k2 = *(const uint4*)(g_Kbf + (size_t)j2 * HID + lane * 8);
            uint4 k3 = *(const uint4*)(g_Kbf + (size_t)j3 * HID + lane * 8);
            float d0 = dot8(qa, qb, k0);
            float d1 = dot8(qa, qb, k1);
            float d2 = dot8(qa, qb, k2);
            float d3 = dot8(qa, qb, k3);
            d0 += __shfl_xor_sync(0xffffffffu, d0, 1);
            d1 += __shfl_xor_sync(0xffffffffu, d1, 1);
            d2 += __shfl_xor_sync(0xffffffffu, d2, 1);
            d3 += __shfl_xor_sync(0xffffffffu, d3, 1);
            d0 += __shfl_xor_sync(0xffffffffu, d0, 2);
            d1 += __shfl_xor_sync(0xffffffffu, d1, 2);
            d2 += __shfl_xor_sync(0xffffffffu, d2, 2);
            d3 += __shfl_xor_sync(0xffffffffu, d3, 2);
            d0 += __shfl_xor_sync(0xffffffffu, d0, 4);
            d1 += __shfl_xor_sync(0xffffffffu, d1, 4);
            d2 += __shfl_xor_sync(0xffffffffu, d2, 4);
            d3 += __shfl_xor_sync(0xffffffffu, d3, 4);
            if ((lane & 7) == 0) {
                int hh = lane >> 3;
                sf[p * 4 + hh] = d0;
                sf[(p + 8) * 4 + hh] = d1;
                sf[(p + 16) * 4 + hh] = d2;
                sf[(p + 24) * 4 + hh] = d3;
            }
        }
        for (; p < nact; p += 8) {
            int jj = list[p];
            uint4 kr = *(const uint4*)(g_Kbf + (size_t)jj * HID + lane * 8);
            float dp = dot8(qa, qb, kr);
            dp += __shfl_xor_sync(0xffffffffu, dp, 1);
            dp += __shfl_xor_sync(0xffffffffu, dp, 2);
            dp += __shfl_xor_sync(0xffffffffu, dp, 4);
            if ((lane & 7) == 0) sf[p * 4 + (lane >> 3)] = dp;
        }
    }
    __syncthreads();

    // ---- B2a pass 1: thread-per-pair edge bias + block max ----
    float mx0 = -INFINITY, mx1 = -INFINITY, mx2 = -INFINITY, mx3 = -INFINITY;
    for (int p = t; p < nact; p += 256) {
        float4 s = sarr[p];
        const int jj = list[p];
        float4 xp = g_xp4[jj];
        float rx = xp.x - xlx, ry = xp.y - xly, rz = xp.z - xlz;
        float d = sqrtf(rx * rx + ry * ry + rz * rz);
        float tp = d * ((float)(TABN - 1) / CUTOFF);
        int k0 = (int)tp;
        k0 = (k0 > TABN - 2) ? (TABN - 2) : k0;
        float fr = tp - (float)k0;
        float4 f0 = g_tab[k0], f1 = g_tab[k0 + 1];
        s.x += f0.x + fr * (f1.x - f0.x);
        s.y += f0.y + fr * (f1.y - f0.y);
        s.z += f0.z + fr * (f1.z - f0.z);
        s.w += f0.w + fr * (f1.w - f0.w);
        sarr[p] = s;
        mx0 = fmaxf(mx0, s.x); mx1 = fmaxf(mx1, s.y);
        mx2 = fmaxf(mx2, s.z); mx3 = fmaxf(mx3, s.w);
    }
    mx0 = wmax(mx0); mx1 = wmax(mx1); mx2 = wmax(mx2); mx3 = wmax(mx3);
    if (lane == 0) { wred[w][0] = mx0; wred[w][1] = mx1; wred[w][2] = mx2; wred[w][3] = mx3; }
    __syncthreads();
    if (t < 4) {
        float m = -INFINITY;
#pragma unroll
        for (int w2 = 0; w2 < 8; w2++) m = fmaxf(m, wred[w2][t]);
        m_s[t] = m;
    }
    __syncthreads();

    // ---- B2a pass 2: warp-per-head exp + l-sums + coord sums ----
    {
        const int hh = w & 3;
        const int half = w >> 2;
        const float mh = m_s[hh];
        float* sf = (float*)sarr;
        float l = 0.f, cx = 0.f, cy = 0.f, cz = 0.f;
        for (int p = half * 32 + lane; p < nact; p += 64) {
            float s = sf[p * 4 + hh];
            float pe = __expf(s - mh);
            sf[p * 4 + hh] = pe;
            l += pe;
            const int jj = list[p];
            float4 xp = g_xp4[jj];
            float rx = xp.x - xlx, ry = xp.y - xly, rz = xp.z - xlz;
            float d2 = rx * rx + ry * ry + rz * rz;
            float invd = rsqrtf(d2 + 1e-16f);
            float pin = pe * invd;
            cx = fmaf(pin, rx, cx); cy = fmaf(pin, ry, cy); cz = fmaf(pin, rz, cz);
        }
        l = wsum(l); cx = wsum(cx); cy = wsum(cy); cz = wsum(cz);
        if (lane == 0) {
            wred[w][0] = l;
            wc[w][0] = cx; wc[w][1] = cy; wc[w][2] = cz;
        }
    }
    __syncthreads();
    if (t < 4) {
        float L = wred[t][0] + wred[t + 4][0];
        linv_s[t] = (L > 0.f) ? __fdividef(1.0f, L) : 0.f;
    }
    if (t >= 32 && t < 44) {
        int j = t - 32;
        int h2 = j / 3, ax = j % 3;
        c12[j] = wc[h2][ax] + wc[h2 + 4][ax];
    }
    __syncthreads();
    if (t < 3) {
        float v = 0.f;
#pragma unroll
        for (int h2 = 0; h2 < 4; h2++) v += c12[h2 * 3 + t] * linv_s[h2];
        ((float*)&g_cm[i])[t] = 0.25f * v;
    }

    // ---- B2b: warp-per-pair weighted V accumulation, 4-way unrolled ----
    float av[8];
#pragma unroll
    for (int k = 0; k < 8; k++) av[k] = 0.f;
    {
        const float* pef = (const float*)sarr;
        int p = w;
        for (; p + 24 < nact; p += 32) {
            int j0 = list[p], j1 = list[p + 8], j2 = list[p + 16], j3 = list[p + 24];
            float pe0 = pef[p * 4 + h];
            float pe1 = pef[(p + 8) * 4 + h];
            float pe2 = pef[(p + 16) * 4 + h];
            float pe3 = pef[(p + 24) * 4 + h];
            uint4 r0 = *(const uint4*)(g_Vbf + (size_t)j0 * HID + lane * 8);
            uint4 r1 = *(const uint4*)(g_Vbf + (size_t)j1 * HID + lane * 8);
            uint4 r2 = *(const uint4*)(g_Vbf + (size_t)j2 * HID + lane * 8);
            uint4 r3 = *(const uint4*)(g_Vbf + (size_t)j3 * HID + lane * 8);
#pragma unroll
            for (int q4 = 0; q4 < 4; q4++) {
                uint4 rr = q4 == 0 ? r0 : (q4 == 1 ? r1 : (q4 == 2 ? r2 : r3));
                float pe = q4 == 0 ? pe0 : (q4 == 1 ? pe1 : (q4 == 2 ? pe2 : pe3));
                float2 v0 = __bfloat1622float2(*(const __nv_bfloat162*)&rr.x);
                float2 v1 = __bfloat1622float2(*(const __nv_bfloat162*)&rr.y);
                float2 v2 = __bfloat1622float2(*(const __nv_bfloat162*)&rr.z);
                float2 v3 = __bfloat1622float2(*(const __nv_bfloat162*)&rr.w);
                av[0] = fmaf(pe, v0.x, av[0]); av[1] = fmaf(pe, v0.y, av[1]);
                av[2] = fmaf(pe, v1.x, av[2]); av[3] = fmaf(pe, v1.y, av[3]);
                av[4] = fmaf(pe, v2.x, av[4]); av[5] = fmaf(pe, v2.y, av[5]);
                av[6] = fmaf(pe, v3.x, av[6]); av[7] = fmaf(pe, v3.y, av[7]);
            }
        }
        for (; p < nact; p += 8) {
            int jj = list[p];
            float pe = pef[p * 4 + h];
            uint4 vr = *(const uint4*)(g_Vbf + (size_t)jj * HID + lane * 8);
            float2 v0 = __bfloat1622float2(*(const __nv_bfloat162*)&vr.x);
            float2 v1 = __bfloat1622float2(*(const __nv_bfloat162*)&vr.y);
            float2 v2 = __bfloat1622float2(*(const __nv_bfloat162*)&vr.z);
            float2 v3 = __bfloat1622float2(*(const __nv_bfloat162*)&vr.w);
            av[0] = fmaf(pe, v0.x, av[0]); av[1] = fmaf(pe, v0.y, av[1]);
            av[2] = fmaf(pe, v1.x, av[2]); av[3] = fmaf(pe, v1.y, av[3]);
            av[4] = fmaf(pe, v2.x, av[4]); av[5] = fmaf(pe, v2.y, av[5]);
            av[6] = fmaf(pe, v3.x, av[6]); av[7] = fmaf(pe, v3.y, av[7]);
        }
    }
#pragma unroll
    for (int k = 0; k < 8; k++) wv[w][lane * 8 + k] = av[k];
    __syncthreads();
    {
        float hv = 0.f;
#pragma unroll
        for (int w2 = 0; w2 < 8; w2++) hv += wv[w2][t];
        g_hattbf[(size_t)i * HID + t] = __float2bfloat16(hv * linv_s[t >> 6]);
    }
    __syncthreads();

    }  // ligand loop
}

// ---------------- finalize: coord scale + x_out ----------------
__global__ __launch_bounds__(256) void finalize_kernel(const float* __restrict__ x_lig,
                                                       const float* __restrict__ c2w,
                                                       const float* __restrict__ c2b,
                                                       float* __restrict__ out) {
    const int lig = blockIdx.x * 8 + (threadIdx.x >> 5);
    const int lane = threadIdx.x & 31;
    const float4* t2 = (const float4*)(g_t2 + (size_t)lig * HID) + lane * 2;
    float4 a = t2[0], b = t2[1];
    const float4* cw = (const float4*)c2w + lane * 2;
    float4 ca = cw[0], cb = cw[1];
    float s = 0.f;
    s = fmaf(a.x / (1.f + __expf(-a.x)), ca.x, s);
    s = fmaf(a.y / (1.f + __expf(-a.y)), ca.y, s);
    s = fmaf(a.z / (1.f + __expf(-a.z)), ca.z, s);
    s = fmaf(a.w / (1.f + __expf(-a.w)), ca.w, s);
    s = fmaf(b.x / (1.f + __expf(-b.x)), cb.x, s);
    s = fmaf(b.y / (1.f + __expf(-b.y)), cb.y, s);
    s = fmaf(b.z / (1.f + __expf(-b.z)), cb.z, s);
    s = fmaf(b.w / (1.f + __expf(-b.w)), cb.w, s);
    s = wsum(s);
    if (lane == 0) {
        s += c2b[0];
        float4 cm = g_cm[lig];
        float* ox = out + (size_t)NLIG * HID + lig * 3;
        ox[0] = x_lig[lig * 3 + 0] + s * cm.x;
        ox[1] = x_lig[lig * 3 + 1] + s * cm.y;
        ox[2] = x_lig[lig * 3 + 2] + s * cm.z;
    }
}

// ---------------- launch ----------------
extern "C" void kernel_launch(void* const* d_in, const int* in_sizes, int n_in,
                              void* d_out, int out_size) {
    const float* h_lig = (const float*)d_in[0];
    const float* x_lig = (const float*)d_in[1];
    const float* h_atm = (const float*)d_in[2];
    const float* x_pkt = (const float*)d_in[3];
    const float* qw = (const float*)d_in[4];
    const float* qb = (const float*)d_in[5];
    const float* kw = (const float*)d_in[6];
    const float* kb = (const float*)d_in[7];
    const float* vw = (const float*)d_in[8];
    const float* vb = (const float*)d_in[9];
    const float* ow = (const float*)d_in[10];
    const float* ob = (const float*)d_in[11];
    const float* e1w = (const float*)d_in[12];
    const float* e1b = (const float*)d_in[13];
    const float* e2w = (const float*)d_in[14];
    const float* e2b = (const float*)d_in[15];
    const float* c1w = (const float*)d_in[16];
    const float* c1b = (const float*)d_in[17];
    const float* c2w = (const float*)d_in[18];
    const float* c2b = (const float*)d_in[19];
    float* out = (float*)d_out;

    __nv_bfloat16 *Abf, *hligbf, *kwbf, *vwbf, *qwbf, *owbf, *c1wbf, *Kbf, *Vbf, *hattbf;
    float *Qp, *t2p;
    cudaGetSymbolAddress((void**)&Abf, g_Abf);
    cudaGetSymbolAddress((void**)&hligbf, g_hligbf);
    cudaGetSymbolAddress((void**)&kwbf, g_kwbf);
    cudaGetSymbolAddress((void**)&vwbf, g_vwbf);
    cudaGetSymbolAddress((void**)&qwbf, g_qwbf);
    cudaGetSymbolAddress((void**)&owbf, g_owbf);
    cudaGetSymbolAddress((void**)&c1wbf, g_c1wbf);
    cudaGetSymbolAddress((void**)&Kbf, g_Kbf);
    cudaGetSymbolAddress((void**)&Vbf, g_Vbf);
    cudaGetSymbolAddress((void**)&hattbf, g_hattbf);
    cudaGetSymbolAddress((void**)&Qp, g_Q);
    cudaGetSymbolAddress((void**)&t2p, g_t2);

    prep_misc<<<48, 256>>>(x_pkt, e1w, e1b, e2w, e2b);
    f2bf_all<<<1200, 256>>>(h_atm, h_lig, kw, vw, qw, ow, c1w);
    gemm_mma<true><<<dim3(NLIG / 64, HID / 64), 256>>>(hligbf, qwbf, qb, nullptr, Qp, NLIG, HID, HID);
    gemm_mma<false><<<dim3(NPKT / 64, HID / 64), 256>>>(Abf, kwbf, kb, nullptr, Kbf, NPKT, HID, ADIM);
    gemm_mma<false><<<dim3(NPKT / 64, HID / 64), 256>>>(Abf, vwbf, vb, nullptr, Vbf, NPKT, HID, ADIM);
    attn_kernel<<<ATTN_GRID, 256>>>(x_lig);
    // h_out = h_lig + h_att @ ow + ob (tensor core, residual fused)
    gemm_mma<true><<<dim3(NLIG / 64, HID / 64), 256>>>(hattbf, owbf, ob, h_lig, out, NLIG, HID, HID);
    // t2 = h_att @ c1w + c1b
    gemm_mma<true><<<dim3(NLIG / 64, HID / 64), 256>>>(hattbf, c1wbf, c1b, nullptr, t2p, NLIG, HID, HID);
    finalize_kernel<<<NLIG / 8, 256>>>(x_lig, c2w, c2b, out);
}

// round 9
// speedup vs baseline: 2.2106x; 1.0557x over previous
#include <cuda_runtime.h>
#include <cuda_bf16.h>
#include <math.h>
#include <stdint.h>

#define NLIG 1024
#define NPKT 8192
#define HID 256
#define ADIM 512
#define TABN 4096
#define CUTOFF 10.0f
#define CAP 1536
#define ATTN_GRID 512

// ---------------- device scratch ----------------
__device__ __nv_bfloat16 g_Abf[NPKT * ADIM];
__device__ __nv_bfloat16 g_hligbf[NLIG * HID];
__device__ __nv_bfloat16 g_kwbf[ADIM * HID];
__device__ __nv_bfloat16 g_vwbf[ADIM * HID];
__device__ __nv_bfloat16 g_qwbf[HID * HID];
__device__ __nv_bfloat16 g_owbf[HID * HID];
__device__ __nv_bfloat16 g_c1wbf[HID * HID];
__device__ __nv_bfloat16 g_Kbf[NPKT * HID];
__device__ __nv_bfloat16 g_Vbf[NPKT * HID];
__device__ __nv_bfloat16 g_hattbf[NLIG * HID];
__device__ float  g_Q[NLIG * HID];
__device__ float  g_t2[NLIG * HID];
__device__ float4 g_cm[NLIG];
__device__ float4 g_xp4[NPKT];
__device__ float4 g_tab[TABN];

// ---------------- helpers ----------------
__device__ __forceinline__ float wsum(float v) {
    v += __shfl_xor_sync(0xffffffffu, v, 16);
    v += __shfl_xor_sync(0xffffffffu, v, 8);
    v += __shfl_xor_sync(0xffffffffu, v, 4);
    v += __shfl_xor_sync(0xffffffffu, v, 2);
    v += __shfl_xor_sync(0xffffffffu, v, 1);
    return v;
}
__device__ __forceinline__ float wmax(float v) {
    v = fmaxf(v, __shfl_xor_sync(0xffffffffu, v, 16));
    v = fmaxf(v, __shfl_xor_sync(0xffffffffu, v, 8));
    v = fmaxf(v, __shfl_xor_sync(0xffffffffu, v, 4));
    v = fmaxf(v, __shfl_xor_sync(0xffffffffu, v, 2));
    v = fmaxf(v, __shfl_xor_sync(0xffffffffu, v, 1));
    return v;
}
__device__ __forceinline__ uint32_t smem_u32(const void* p) {
    return (uint32_t)__cvta_generic_to_shared(p);
}
__device__ __forceinline__ void cp_async16(uint32_t dst, const void* src) {
    asm volatile("cp.async.cg.shared.global [%0], [%1], 16;" :: "r"(dst), "l"(src));
}
__device__ __forceinline__ float dot8(const float4& qa, const float4& qb, const uint4& kr) {
    float2 k0 = __bfloat1622float2(*(const __nv_bfloat162*)&kr.x);
    float2 k1 = __bfloat1622float2(*(const __nv_bfloat162*)&kr.y);
    float2 k2 = __bfloat1622float2(*(const __nv_bfloat162*)&kr.z);
    float2 k3 = __bfloat1622float2(*(const __nv_bfloat162*)&kr.w);
    return qa.x * k0.x + qa.y * k0.y + qa.z * k1.x + qa.w * k1.y +
           qb.x * k2.x + qb.y * k2.y + qb.z * k3.x + qb.w * k3.y;
}

// ---------------- fused prep: table (blocks 0-15) + xp4 (blocks 16-47) ----
__global__ void prep_misc(const float* __restrict__ xp,
                          const float* __restrict__ e1w,
                          const float* __restrict__ e1b,
                          const float* __restrict__ e2w,
                          const float* __restrict__ e2b) {
    int b = blockIdx.x, t = threadIdx.x;
    if (b < 16) {
        int e = b * 256 + t;
        float d = (float)e * (CUTOFF / (float)(TABN - 1));
        float a0 = e2b[0], a1 = e2b[1], a2 = e2b[2], a3 = e2b[3];
        for (int u = 0; u < HID; u++) {
            float z = fmaf(d, e1w[u], e1b[u]);
            float s = z / (1.0f + expf(-z));
            a0 = fmaf(s, e2w[u * 4 + 0], a0);
            a1 = fmaf(s, e2w[u * 4 + 1], a1);
            a2 = fmaf(s, e2w[u * 4 + 2], a2);
            a3 = fmaf(s, e2w[u * 4 + 3], a3);
        }
        g_tab[e] = make_float4(a0, a1, a2, a3);
    } else {
        int j = (b - 16) * 256 + t;
        g_xp4[j] = make_float4(xp[j * 3 + 0], xp[j * 3 + 1], xp[j * 3 + 2], 0.f);
    }
}

// ---------------- fp32 -> bf16, 4 independent float4 per thread ----------
__global__ __launch_bounds__(256) void f2bf_all(const float* __restrict__ h_atm,
                                                const float* __restrict__ h_lig,
                                                const float* __restrict__ kw,
                                                const float* __restrict__ vw,
                                                const float* __restrict__ qw,
                                                const float* __restrict__ ow,
                                                const float* __restrict__ c1w) {
    int b = blockIdx.x, t = threadIdx.x;
    const float* src;
    __nv_bfloat16* dst;
    int b0;
    if (b < 1024)      { src = h_atm; dst = g_Abf;    b0 = b; }
    else if (b < 1088) { src = h_lig; dst = g_hligbf; b0 = b - 1024; }
    else if (b < 1104) { src = qw;    dst = g_qwbf;   b0 = b - 1088; }
    else if (b < 1136) { src = kw;    dst = g_kwbf;   b0 = b - 1104; }
    else if (b < 1168) { src = vw;    dst = g_vwbf;   b0 = b - 1136; }
    else if (b < 1184) { src = ow;    dst = g_owbf;   b0 = b - 1168; }
    else               { src = c1w;   dst = g_c1wbf;  b0 = b - 1184; }
    int f4 = b0 * 1024 + t;
#pragma unroll
    for (int r = 0; r < 4; r++) {
        int idx = (f4 + r * 256) * 4;
        float4 v = *(const float4*)(src + idx);
        *(__nv_bfloat162*)(dst + idx)     = __floats2bfloat162_rn(v.x, v.y);
        *(__nv_bfloat162*)(dst + idx + 2) = __floats2bfloat162_rn(v.z, v.w);
    }
}

// ---------------- bf16 tensor-core GEMM body (shared by QKV and EPI) ------
// BM=64, BN=64, BK=32; 2-stage cp.async pipeline.
__device__ __forceinline__ void gemm_body(const __nv_bfloat16* __restrict__ A,
                                          const __nv_bfloat16* __restrict__ W,
                                          const float* __restrict__ bias,
                                          const float* __restrict__ R,
                                          void* __restrict__ Cv,
                                          int N, int K, bool floatout) {
    __shared__ __nv_bfloat16 As[2][64][40];
    __shared__ __nv_bfloat16 Bs[2][32][72];
    const int t = threadIdx.x;
    const int warp = t >> 5, lane = t & 31;
    const int wm = warp >> 1, wn = warp & 1;
    const int bm = blockIdx.x * 64, bn = blockIdx.y * 64;
    const int ar = t >> 2, ac = (t & 3) * 8;
    const int br = t >> 3, bc = (t & 7) * 8;

    float acc[4][4];
#pragma unroll
    for (int nt = 0; nt < 4; nt++)
#pragma unroll
        for (int r = 0; r < 4; r++) acc[nt][r] = 0.f;

    const int NK = K / 32;
    cp_async16(smem_u32(&As[0][ar][ac]), A + (size_t)(bm + ar) * K + ac);
    cp_async16(smem_u32(&Bs[0][br][bc]), W + (size_t)br * N + bn + bc);
    asm volatile("cp.async.commit_group;");

    for (int kt = 0; kt < NK; kt++) {
        if (kt + 1 < NK) {
            int s = (kt + 1) & 1, ko = (kt + 1) * 32;
            cp_async16(smem_u32(&As[s][ar][ac]), A + (size_t)(bm + ar) * K + ko + ac);
            cp_async16(smem_u32(&Bs[s][br][bc]), W + (size_t)(ko + br) * N + bn + bc);
            asm volatile("cp.async.commit_group;");
            asm volatile("cp.async.wait_group 1;");
        } else {
            asm volatile("cp.async.wait_group 0;");
        }
        __syncthreads();
        const int st = kt & 1;
#pragma unroll
        for (int kk = 0; kk < 32; kk += 16) {
            uint32_t a[4];
            {
                int row = wm * 16 + (lane & 15);
                int col = kk + 8 * (lane >> 4);
                uint32_t addr = smem_u32(&As[st][row][col]);
                asm volatile("ldmatrix.sync.aligned.m8n8.x4.shared.b16 {%0,%1,%2,%3}, [%4];"
                             : "=r"(a[0]), "=r"(a[1]), "=r"(a[2]), "=r"(a[3])
                             : "r"(addr));
            }
            uint32_t b[4][2];
#pragma unroll
            for (int nt2 = 0; nt2 < 2; nt2++) {
                int row = kk + (lane & 15);
                int col = wn * 32 + nt2 * 16 + 8 * (lane >> 4);
                uint32_t addr = smem_u32(&Bs[st][row][col]);
                uint32_t b0, b1, b2, b3;
                asm volatile("ldmatrix.sync.aligned.m8n8.x4.trans.shared.b16 {%0,%1,%2,%3}, [%4];"
                             : "=r"(b0), "=r"(b1), "=r"(b2), "=r"(b3)
                             : "r"(addr));
                b[nt2 * 2 + 0][0] = b0; b[nt2 * 2 + 0][1] = b1;
                b[nt2 * 2 + 1][0] = b2; b[nt2 * 2 + 1][1] = b3;
            }
#pragma unroll
            for (int nt = 0; nt < 4; nt++) {
                asm volatile(
                    "mma.sync.aligned.m16n8k16.row.col.f32.bf16.bf16.f32 "
                    "{%0,%1,%2,%3}, {%4,%5,%6,%7}, {%8,%9}, {%0,%1,%2,%3};"
                    : "+f"(acc[nt][0]), "+f"(acc[nt][1]), "+f"(acc[nt][2]), "+f"(acc[nt][3])
                    : "r"(a[0]), "r"(a[1]), "r"(a[2]), "r"(a[3]),
                      "r"(b[nt][0]), "r"(b[nt][1]));
            }
        }
        __syncthreads();
    }

#pragma unroll
    for (int nt = 0; nt < 4; nt++) {
        int row0 = bm + wm * 16 + (lane >> 2);
        int col = bn + wn * 32 + nt * 8 + (lane & 3) * 2;
        float bi0 = bias[col], bi1 = bias[col + 1];
        float v0 = acc[nt][0] + bi0, v1 = acc[nt][1] + bi1;
        float v2 = acc[nt][2] + bi0, v3 = acc[nt][3] + bi1;
        if (R) {
            float2 r0 = *(const float2*)(R + (size_t)row0 * N + col);
            float2 r1 = *(const float2*)(R + (size_t)(row0 + 8) * N + col);
            v0 += r0.x; v1 += r0.y; v2 += r1.x; v3 += r1.y;
        }
        if (floatout) {
            float* C = (float*)Cv;
            *(float2*)(C + (size_t)row0 * N + col) = make_float2(v0, v1);
            *(float2*)(C + (size_t)(row0 + 8) * N + col) = make_float2(v2, v3);
        } else {
            __nv_bfloat16* C = (__nv_bfloat16*)Cv;
            *(__nv_bfloat162*)(C + (size_t)row0 * N + col) = __floats2bfloat162_rn(v0, v1);
            *(__nv_bfloat162*)(C + (size_t)(row0 + 8) * N + col) = __floats2bfloat162_rn(v2, v3);
        }
    }
}

// ---------------- fused Q/K/V projection: grid.z selects layer ----------
__global__ __launch_bounds__(256) void gemm_qkv(const float* __restrict__ qb,
                                                const float* __restrict__ kb,
                                                const float* __restrict__ vb) {
    if (blockIdx.z == 0) {
        if (blockIdx.x >= NLIG / 64) return;
        gemm_body(g_hligbf, g_qwbf, qb, nullptr, (void*)g_Q, HID, HID, true);
    } else if (blockIdx.z == 1) {
        gemm_body(g_Abf, g_kwbf, kb, nullptr, (void*)g_Kbf, HID, ADIM, false);
    } else {
        gemm_body(g_Abf, g_vwbf, vb, nullptr, (void*)g_Vbf, HID, ADIM, false);
    }
}

// ---------------- fused epilogue GEMMs: grid.z selects ------------------
__global__ __launch_bounds__(256) void gemm_epi(const float* __restrict__ ob,
                                                const float* __restrict__ c1b,
                                                const float* __restrict__ h_lig,
                                                float* __restrict__ out) {
    if (blockIdx.z == 0) {
        gemm_body(g_hattbf, g_owbf, ob, h_lig, (void*)out, HID, HID, true);
    } else {
        gemm_body(g_hattbf, g_c1wbf, c1b, nullptr, (void*)g_t2, HID, HID, true);
    }
}

// ---------------- attention kernel: persistent, 2 ligands per block ------
__global__ __launch_bounds__(256, 4) void attn_kernel(const float* __restrict__ x_lig) {
    const int t = threadIdx.x;
    const int w = t >> 5, lane = t & 31;
    const int h = lane >> 3;

    __shared__ float q_s[HID];
    __shared__ unsigned short list[CAP];
    __shared__ float4 sarr[CAP];
    __shared__ float wv[8][HID];
    __shared__ float wred[8][4];
    __shared__ float wc[8][4];
    __shared__ float m_s[4], linv_s[4];
    __shared__ float c12[12];
    __shared__ int woff[8];
    __shared__ int s_cnt;
    __shared__ float s_xl[3];

    for (int i = blockIdx.x; i < NLIG; i += ATTN_GRID) {

    if (t < 3) s_xl[t] = x_lig[i * 3 + t];
    q_s[t] = g_Q[(size_t)i * HID + t] * 0.125f;
    __syncthreads();
    const float xlx = s_xl[0], xly = s_xl[1], xlz = s_xl[2];

    // ---- Phase A: deterministic compaction ----
    unsigned msk = 0;
    const int jbase = t * 32;
#pragma unroll 4
    for (int k = 0; k < 32; k++) {
        float4 xp = g_xp4[jbase + k];
        float rx = xp.x - xlx, ry = xp.y - xly, rz = xp.z - xlz;
        float d2 = rx * rx + ry * ry + rz * rz;
        if (d2 < CUTOFF * CUTOFF) msk |= (1u << k);
    }
    int mycnt = __popc(msk);
    int inc = mycnt;
#pragma unroll
    for (int off = 1; off < 32; off <<= 1) {
        int v = __shfl_up_sync(0xffffffffu, inc, off);
        if (lane >= off) inc += v;
    }
    if (lane == 31) woff[w] = inc;
    __syncthreads();
    if (t == 0) {
        int run = 0;
#pragma unroll
        for (int ww = 0; ww < 8; ww++) { int v = woff[ww]; woff[ww] = run; run += v; }
        s_cnt = run;
    }
    __syncthreads();
    int offset = woff[w] + (inc - mycnt);
    unsigned mm = msk;
    while (mm) {
        int k = __ffs(mm) - 1;
        mm &= mm - 1;
        if (offset < CAP) list[offset] = (unsigned short)(jbase + k);
        offset++;
    }
    __syncthreads();
    const int nact = (s_cnt < CAP) ? s_cnt : CAP;

    // ---- B1: warp-per-pair Q.K dots, 4-way unrolled gather ----
    {
        const float4 qa = ((const float4*)q_s)[lane * 2];
        const float4 qb = ((const float4*)q_s)[lane * 2 + 1];
        float* sf = (float*)sarr;
        int p = w;
        for (; p + 24 < nact; p += 32) {
            int j0 = list[p], j1 = list[p + 8], j2 = list[p + 16], j3 = list[p + 24];
            uint4 k0 = *(const uint4*)(g_Kbf + (size_t)j0 * HID + lane * 8);
            uint4 k1 = *(const uint4*)(g_Kbf + (size_t)j1 * HID + lane * 8);
            uint4 k2 = *(const uint4*)(g_Kbf + (size_t)j2 * HID + lane * 8);
            uint4 k3 = *(const uint4*)(g_Kbf + (size_t)j3 * HID + lane * 8);
            float d0 = dot8(qa, qb, k0);
            float d1 = dot8(qa, qb, k1);
            float d2 = dot8(qa, qb, k2);
            float d3 = dot8(qa, qb, k3);
            d0 += __shfl_xor_sync(0xffffffffu, d0, 1);
            d1 += __shfl_xor_sync(0xffffffffu, d1, 1);
            d2 += __shfl_xor_sync(0xffffffffu, d2, 1);
            d3 += __shfl_xor_sync(0xffffffffu, d3, 1);
            d0 += __shfl_xor_sync(0xffffffffu, d0, 2);
            d1 += __shfl_xor_sync(0xffffffffu, d1, 2);
            d2 += __shfl_xor_sync(0xffffffffu, d2, 2);
            d3 += __shfl_xor_sync(0xffffffffu, d3, 2);
            d0 += __shfl_xor_sync(0xffffffffu, d0, 4);
            d1 += __shfl_xor_sync(0xffffffffu, d1, 4);
            d2 += __shfl_xor_sync(0xffffffffu, d2, 4);
            d3 += __shfl_xor_sync(0xffffffffu, d3, 4);
            if ((lane & 7) == 0) {
                int hh = lane >> 3;
                sf[p * 4 + hh] = d0;
                sf[(p + 8) * 4 + hh] = d1;
                sf[(p + 16) * 4 + hh] = d2;
                sf[(p + 24) * 4 + hh] = d3;
            }
        }
        for (; p < nact; p += 8) {
            int jj = list[p];
            uint4 kr = *(const uint4*)(g_Kbf + (size_t)jj * HID + lane * 8);
            float dp = dot8(qa, qb, kr);
            dp += __shfl_xor_sync(0xffffffffu, dp, 1);
            dp += __shfl_xor_sync(0xffffffffu, dp, 2);
            dp += __shfl_xor_sync(0xffffffffu, dp, 4);
            if ((lane & 7) == 0) sf[p * 4 + (lane >> 3)] = dp;
        }
    }
    __syncthreads();

    // ---- B2a pass 1: thread-per-pair edge bias + block max ----
    float mx0 = -INFINITY, mx1 = -INFINITY, mx2 = -INFINITY, mx3 = -INFINITY;
    for (int p = t; p < nact; p += 256) {
        float4 s = sarr[p];
        const int jj = list[p];
        float4 xp = g_xp4[jj];
        float rx = xp.x - xlx, ry = xp.y - xly, rz = xp.z - xlz;
        float d = sqrtf(rx * rx + ry * ry + rz * rz);
        float tp = d * ((float)(TABN - 1) / CUTOFF);
        int k0 = (int)tp;
        k0 = (k0 > TABN - 2) ? (TABN - 2) : k0;
        float fr = tp - (float)k0;
        float4 f0 = g_tab[k0], f1 = g_tab[k0 + 1];
        s.x += f0.x + fr * (f1.x - f0.x);
        s.y += f0.y + fr * (f1.y - f0.y);
        s.z += f0.z + fr * (f1.z - f0.z);
        s.w += f0.w + fr * (f1.w - f0.w);
        sarr[p] = s;
        mx0 = fmaxf(mx0, s.x); mx1 = fmaxf(mx1, s.y);
        mx2 = fmaxf(mx2, s.z); mx3 = fmaxf(mx3, s.w);
    }
    mx0 = wmax(mx0); mx1 = wmax(mx1); mx2 = wmax(mx2); mx3 = wmax(mx3);
    if (lane == 0) { wred[w][0] = mx0; wred[w][1] = mx1; wred[w][2] = mx2; wred[w][3] = mx3; }
    __syncthreads();
    if (t < 4) {
        float m = -INFINITY;
#pragma unroll
        for (int w2 = 0; w2 < 8; w2++) m = fmaxf(m, wred[w2][t]);
        m_s[t] = m;
    }
    __syncthreads();

    // ---- B2a pass 2: warp-per-head exp + l-sums + coord sums ----
    {
        const int hh = w & 3;
        const int half = w >> 2;
        const float mh = m_s[hh];
        float* sf = (float*)sarr;
        float l = 0.f, cx = 0.f, cy = 0.f, cz = 0.f;
        for (int p = half * 32 + lane; p < nact; p += 64) {
            float s = sf[p * 4 + hh];
            float pe = __expf(s - mh);
            sf[p * 4 + hh] = pe;
            l += pe;
            const int jj = list[p];
            float4 xp = g_xp4[jj];
            float rx = xp.x - xlx, ry = xp.y - xly, rz = xp.z - xlz;
            float d2 = rx * rx + ry * ry + rz * rz;
            float invd = rsqrtf(d2 + 1e-16f);
            float pin = pe * invd;
            cx = fmaf(pin, rx, cx); cy = fmaf(pin, ry, cy); cz = fmaf(pin, rz, cz);
        }
        l = wsum(l); cx = wsum(cx); cy = wsum(cy); cz = wsum(cz);
        if (lane == 0) {
            wred[w][0] = l;
            wc[w][0] = cx; wc[w][1] = cy; wc[w][2] = cz;
        }
    }
    __syncthreads();
    if (t < 4) {
        float L = wred[t][0] + wred[t + 4][0];
        linv_s[t] = (L > 0.f) ? __fdividef(1.0f, L) : 0.f;
    }
    if (t >= 32 && t < 44) {
        int j = t - 32;
        int h2 = j / 3, ax = j % 3;
        c12[j] = wc[h2][ax] + wc[h2 + 4][ax];
    }
    __syncthreads();
    if (t < 3) {
        float v = 0.f;
#pragma unroll
        for (int h2 = 0; h2 < 4; h2++) v += c12[h2 * 3 + t] * linv_s[h2];
        ((float*)&g_cm[i])[t] = 0.25f * v;
    }

    // ---- B2b: warp-per-pair weighted V accumulation, 4-way unrolled ----
    float av[8];
#pragma unroll
    for (int k = 0; k < 8; k++) av[k] = 0.f;
    {
        const float* pef = (const float*)sarr;
        int p = w;
        for (; p + 24 < nact; p += 32) {
            int j0 = list[p], j1 = list[p + 8], j2 = list[p + 16], j3 = list[p + 24];
            float pe0 = pef[p * 4 + h];
            float pe1 = pef[(p + 8) * 4 + h];
            float pe2 = pef[(p + 16) * 4 + h];
            float pe3 = pef[(p + 24) * 4 + h];
            uint4 r0 = *(const uint4*)(g_Vbf + (size_t)j0 * HID + lane * 8);
            uint4 r1 = *(const uint4*)(g_Vbf + (size_t)j1 * HID + lane * 8);
            uint4 r2 = *(const uint4*)(g_Vbf + (size_t)j2 * HID + lane * 8);
            uint4 r3 = *(const uint4*)(g_Vbf + (size_t)j3 * HID + lane * 8);
#pragma unroll
            for (int q4 = 0; q4 < 4; q4++) {
                uint4 rr = q4 == 0 ? r0 : (q4 == 1 ? r1 : (q4 == 2 ? r2 : r3));
                float pe = q4 == 0 ? pe0 : (q4 == 1 ? pe1 : (q4 == 2 ? pe2 : pe3));
                float2 v0 = __bfloat1622float2(*(const __nv_bfloat162*)&rr.x);
                float2 v1 = __bfloat1622float2(*(const __nv_bfloat162*)&rr.y);
                float2 v2 = __bfloat1622float2(*(const __nv_bfloat162*)&rr.z);
                float2 v3 = __bfloat1622float2(*(const __nv_bfloat162*)&rr.w);
                av[0] = fmaf(pe, v0.x, av[0]); av[1] = fmaf(pe, v0.y, av[1]);
                av[2] = fmaf(pe, v1.x, av[2]); av[3] = fmaf(pe, v1.y, av[3]);
                av[4] = fmaf(pe, v2.x, av[4]); av[5] = fmaf(pe, v2.y, av[5]);
                av[6] = fmaf(pe, v3.x, av[6]); av[7] = fmaf(pe, v3.y, av[7]);
            }
        }
        for (; p < nact; p += 8) {
            int jj = list[p];
            float pe = pef[p * 4 + h];
            uint4 vr = *(const uint4*)(g_Vbf + (size_t)jj * HID + lane * 8);
            float2 v0 = __bfloat1622float2(*(const __nv_bfloat162*)&vr.x);
            float2 v1 = __bfloat1622float2(*(const __nv_bfloat162*)&vr.y);
            float2 v2 = __bfloat1622float2(*(const __nv_bfloat162*)&vr.z);
            float2 v3 = __bfloat1622float2(*(const __nv_bfloat162*)&vr.w);
            av[0] = fmaf(pe, v0.x, av[0]); av[1] = fmaf(pe, v0.y, av[1]);
            av[2] = fmaf(pe, v1.x, av[2]); av[3] = fmaf(pe, v1.y, av[3]);
            av[4] = fmaf(pe, v2.x, av[4]); av[5] = fmaf(pe, v2.y, av[5]);
            av[6] = fmaf(pe, v3.x, av[6]); av[7] = fmaf(pe, v3.y, av[7]);
        }
    }
#pragma unroll
    for (int k = 0; k < 8; k++) wv[w][lane * 8 + k] = av[k];
    __syncthreads();
    {
        float hv = 0.f;
#pragma unroll
        for (int w2 = 0; w2 < 8; w2++) hv += wv[w2][t];
        g_hattbf[(size_t)i * HID + t] = __float2bfloat16(hv * linv_s[t >> 6]);
    }
    __syncthreads();

    }  // ligand loop
}

// ---------------- finalize: coord scale + x_out ----------------
__global__ __launch_bounds__(256) void finalize_kernel(const float* __restrict__ x_lig,
                                                       const float* __restrict__ c2w,
                                                       const float* __restrict__ c2b,
                                                       float* __restrict__ out) {
    const int lig = blockIdx.x * 8 + (threadIdx.x >> 5);
    const int lane = threadIdx.x & 31;
    const float4* t2 = (const float4*)(g_t2 + (size_t)lig * HID) + lane * 2;
    float4 a = t2[0], b = t2[1];
    const float4* cw = (const float4*)c2w + lane * 2;
    float4 ca = cw[0], cb = cw[1];
    float s = 0.f;
    s = fmaf(a.x / (1.f + __expf(-a.x)), ca.x, s);
    s = fmaf(a.y / (1.f + __expf(-a.y)), ca.y, s);
    s = fmaf(a.z / (1.f + __expf(-a.z)), ca.z, s);
    s = fmaf(a.w / (1.f + __expf(-a.w)), ca.w, s);
    s = fmaf(b.x / (1.f + __expf(-b.x)), cb.x, s);
    s = fmaf(b.y / (1.f + __expf(-b.y)), cb.y, s);
    s = fmaf(b.z / (1.f + __expf(-b.z)), cb.z, s);
    s = fmaf(b.w / (1.f + __expf(-b.w)), cb.w, s);
    s = wsum(s);
    if (lane == 0) {
        s += c2b[0];
        float4 cm = g_cm[lig];
        float* ox = out + (size_t)NLIG * HID + lig * 3;
        ox[0] = x_lig[lig * 3 + 0] + s * cm.x;
        ox[1] = x_lig[lig * 3 + 1] + s * cm.y;
        ox[2] = x_lig[lig * 3 + 2] + s * cm.z;
    }
}

// ---------------- launch ----------------
extern "C" void kernel_launch(void* const* d_in, const int* in_sizes, int n_in,
                              void* d_out, int out_size) {
    const float* h_lig = (const float*)d_in[0];
    const float* x_lig = (const float*)d_in[1];
    const float* h_atm = (const float*)d_in[2];
    const float* x_pkt = (const float*)d_in[3];
    const float* qw = (const float*)d_in[4];
    const float* qb = (const float*)d_in[5];
    const float* kw = (const float*)d_in[6];
    const float* kb = (const float*)d_in[7];
    const float* vw = (const float*)d_in[8];
    const float* vb = (const float*)d_in[9];
    const float* ow = (const float*)d_in[10];
    const float* ob = (const float*)d_in[11];
    const float* e1w = (const float*)d_in[12];
    const float* e1b = (const float*)d_in[13];
    const float* e2w = (const float*)d_in[14];
    const float* e2b = (const float*)d_in[15];
    const float* c1w = (const float*)d_in[16];
    const float* c1b = (const float*)d_in[17];
    const float* c2w = (const float*)d_in[18];
    const float* c2b = (const float*)d_in[19];
    float* out = (float*)d_out;

    // launch 0: table + xp4 prep
    prep_misc<<<48, 256>>>(x_pkt, e1w, e1b, e2w, e2b);
    // launch 1: all fp32->bf16 conversions
    f2bf_all<<<1200, 256>>>(h_atm, h_lig, kw, vw, qw, ow, c1w);
    // launch 2: fused Q/K/V projections (z selects layer)
    gemm_qkv<<<dim3(NPKT / 64, HID / 64, 3), 256>>>(qb, kb, vb);
    // launch 3: attention  <-- ncu captured slot
    attn_kernel<<<ATTN_GRID, 256>>>(x_lig);
    // launch 4: fused epilogue GEMMs
    gemm_epi<<<dim3(NLIG / 64, HID / 64, 2), 256>>>(ob, c1b, h_lig, out);
    // launch 5: finalize coords
    finalize_kernel<<<NLIG / 8, 256>>>(x_lig, c2w, c2b, out);
}